// round 2
// baseline (speedup 1.0000x reference)
#include <cuda_runtime.h>

// ForgetMult: h_t = f_t * x_t + (1 - f_t) * h_{t-1}
// Shapes: f, x: (SEQ=4096, BATCH=16, HIDDEN=512) fp32; hidden_init: (16, 512)
// out[t, b, h] = h_t  (inclusive scan result, h_0 = hidden_init)
//
// Strategy: one thread per (batch, hidden) channel (8192 channels total).
// Channel is the fastest-varying index, so per-timestep accesses are fully
// coalesced (each warp reads one 128B line per t). The recurrence is
// rewritten h = a*h + b with a = 1-f, b = f*x computed in the (independent)
// prefetch stage, so the serial dependence is a single FFMA (4 cyc/step).
// Software-pipelined prefetch of U=32 timesteps keeps ~64 LDGs in flight
// per thread to cover DRAM latency despite the low occupancy.

#define SEQ_LEN 4096
#define CHANNELS 8192  // BATCH * HIDDEN = 16 * 512

static constexpr int U = 32;  // timesteps per pipeline stage

__global__ void forget_mult_scan_kernel(
    const float* __restrict__ f,
    const float* __restrict__ x,
    const float* __restrict__ h0,
    float* __restrict__ out)
{
    const int c = blockIdx.x * blockDim.x + threadIdx.x;
    if (c >= CHANNELS) return;

    float h = h0[c];

    const float* fp = f + c;
    const float* xp = x + c;
    float* op = out + c;

    float a[U], b[U];

    // Prologue: load + preprocess first U timesteps.
#pragma unroll
    for (int i = 0; i < U; i++) {
        float ft = __ldcs(fp + (size_t)i * CHANNELS);
        float xt = __ldcs(xp + (size_t)i * CHANNELS);
        a[i] = 1.0f - ft;
        b[i] = ft * xt;
    }

    for (int t0 = 0; t0 < SEQ_LEN; t0 += U) {
        float an[U], bn[U];
        const bool more = (t0 + U) < SEQ_LEN;
        if (more) {
            // Issue next stage's loads before touching the serial chain so
            // they overlap the dependent FMA sequence below.
#pragma unroll
            for (int i = 0; i < U; i++) {
                float ft = __ldcs(fp + (size_t)(t0 + U + i) * CHANNELS);
                float xt = __ldcs(xp + (size_t)(t0 + U + i) * CHANNELS);
                an[i] = 1.0f - ft;
                bn[i] = ft * xt;
            }
        }

        // Serial recurrence: one dependent FFMA per step.
#pragma unroll
        for (int i = 0; i < U; i++) {
            h = fmaf(a[i], h, b[i]);
            __stcs(op + (size_t)(t0 + i) * CHANNELS, h);
        }

        if (more) {
#pragma unroll
            for (int i = 0; i < U; i++) {
                a[i] = an[i];
                b[i] = bn[i];
            }
        }
    }
}

extern "C" void kernel_launch(void* const* d_in, const int* in_sizes, int n_in,
                              void* d_out, int out_size)
{
    const float* f  = (const float*)d_in[0];
    const float* x  = (const float*)d_in[1];
    const float* h0 = (const float*)d_in[2];
    float* out = (float*)d_out;

    // 8192 channels, 32 threads/block -> 256 blocks so work spreads across
    // all 148 SMs (larger blocks would cluster the streams on few SMs).
    dim3 block(32);
    dim3 grid(CHANNELS / 32);
    forget_mult_scan_kernel<<<grid, block>>>(f, x, h0, out);
}

// round 3
// speedup vs baseline: 1.0002x; 1.0002x over previous
#include <cuda_runtime.h>

// ForgetMult: h_t = f_t * x_t + (1 - f_t) * h_{t-1}
// Shapes: f, x: (SEQ=4096, BATCH=16, HIDDEN=512) fp32; hidden_init: (16, 512)
// out[t, b, h] = h_t  (inclusive scan result, h_0 = hidden_init)
//
// Strategy: one thread per (batch, hidden) channel (8192 channels total).
// Channel is the fastest-varying index, so per-timestep accesses are fully
// coalesced (each warp reads one 128B line per t). The recurrence is
// rewritten h = a*h + b with a = 1-f, b = f*x computed in the (independent)
// prefetch stage, so the serial dependence is a single FFMA (4 cyc/step).
// Software-pipelined prefetch of U=32 timesteps keeps ~64 LDGs in flight
// per thread to cover DRAM latency despite the low occupancy.

#define SEQ_LEN 4096
#define CHANNELS 8192  // BATCH * HIDDEN = 16 * 512

static constexpr int U = 32;  // timesteps per pipeline stage

__global__ void forget_mult_scan_kernel(
    const float* __restrict__ f,
    const float* __restrict__ x,
    const float* __restrict__ h0,
    float* __restrict__ out)
{
    const int c = blockIdx.x * blockDim.x + threadIdx.x;
    if (c >= CHANNELS) return;

    float h = h0[c];

    const float* fp = f + c;
    const float* xp = x + c;
    float* op = out + c;

    float a[U], b[U];

    // Prologue: load + preprocess first U timesteps.
#pragma unroll
    for (int i = 0; i < U; i++) {
        float ft = __ldcs(fp + (size_t)i * CHANNELS);
        float xt = __ldcs(xp + (size_t)i * CHANNELS);
        a[i] = 1.0f - ft;
        b[i] = ft * xt;
    }

    for (int t0 = 0; t0 < SEQ_LEN; t0 += U) {
        float an[U], bn[U];
        const bool more = (t0 + U) < SEQ_LEN;
        if (more) {
            // Issue next stage's loads before touching the serial chain so
            // they overlap the dependent FMA sequence below.
#pragma unroll
            for (int i = 0; i < U; i++) {
                float ft = __ldcs(fp + (size_t)(t0 + U + i) * CHANNELS);
                float xt = __ldcs(xp + (size_t)(t0 + U + i) * CHANNELS);
                an[i] = 1.0f - ft;
                bn[i] = ft * xt;
            }
        }

        // Serial recurrence: one dependent FFMA per step.
#pragma unroll
        for (int i = 0; i < U; i++) {
            h = fmaf(a[i], h, b[i]);
            __stcs(op + (size_t)(t0 + i) * CHANNELS, h);
        }

        if (more) {
#pragma unroll
            for (int i = 0; i < U; i++) {
                a[i] = an[i];
                b[i] = bn[i];
            }
        }
    }
}

extern "C" void kernel_launch(void* const* d_in, const int* in_sizes, int n_in,
                              void* d_out, int out_size)
{
    const float* f  = (const float*)d_in[0];
    const float* x  = (const float*)d_in[1];
    const float* h0 = (const float*)d_in[2];
    float* out = (float*)d_out;

    // 8192 channels, 32 threads/block -> 256 blocks so work spreads across
    // all 148 SMs (larger blocks would cluster the streams on few SMs).
    dim3 block(32);
    dim3 grid(CHANNELS / 32);
    forget_mult_scan_kernel<<<grid, block>>>(f, x, h0, out);
}